// round 17
// baseline (speedup 1.0000x reference)
#include <cuda_runtime.h>
#include <cuda_bf16.h>
#include <stdint.h>

#define AG 10
#define SEQ 50
#define IND 6
#define HID 64
#define OUTD 2
#define TDEC 60
#define BATCH 32768
#define THREADS 256
#define MT 64
#define KPAD 168
#define GB 16384                 // bytes per 16-k group (hi 8KB + lo 8KB)

#define STGH_OFF 32768           // ring: 2 x 16KB at offset 0
#define STGL_OFF (STGH_OFF + MT*KPAD*2)
#define LW_OFF   (STGL_OFF + MT*KPAD*2)
#define LB_OFF   (LW_OFF + 512)
#define SM_TOT   (LB_OFF + 16)

// Weights: 28 groups (E0:0-4, E1:5-13, D0:14-18, D1:19-27), each 16KB.
__device__ __align__(16) unsigned char g_Wb[28 * GB];

// ---------------------------------------------------------------------------
// prep: gate-permute + bias-fold + bf16 hi/lo split + B-fragment layout.
// n <-> (j,q): p=n&15, q=((p>>3)<<1)|(p&1), j=((n>>4)<<2)|((p>>1)&3), r=q*64+j.
// k-slot axis: [x/out 0-5 | bias 6 | pad 7 | h0 8-71 | h1 72-135 | pad].
// Block layout: [group][split][n=256][k=16] bf16, k-offset XOR-swizzled by n&4.
// ---------------------------------------------------------------------------
__global__ void prep(
    const float* eWih0, const float* eWhh0, const float* ebih0, const float* ebhh0,
    const float* eWih1, const float* eWhh1, const float* ebih1, const float* ebhh1,
    const float* dWih0, const float* dWhh0, const float* dbih0, const float* dbhh0,
    const float* dWih1, const float* dWhh1, const float* dbih1, const float* dbhh1)
{
    int idx = blockIdx.x * blockDim.x + threadIdx.x;
    if (idx >= 28 * 2 * 4096) return;
    int kk = idx & 15, n = (idx >> 4) & 255, s = (idx >> 12) & 1, g = idx >> 13;
    int p = n & 15;
    int q = ((p >> 3) << 1) | (p & 1);
    int j = ((n >> 4) << 2) | ((p >> 1) & 3);
    int r = q * 64 + j;
    int sec, gl;
    if (g < 5)       { sec = 0; gl = g; }
    else if (g < 14) { sec = 1; gl = g - 5; }
    else if (g < 19) { sec = 2; gl = g - 14; }
    else             { sec = 3; gl = g - 19; }
    int slot = gl * 16 + kk;
    float w = 0.f;
    if (sec == 0) {
        if (slot < 6) w = eWih0[r * IND + slot];
        else if (slot == 6) w = ebih0[r] + ebhh0[r];
        else if (slot >= 8 && slot <= 71) w = eWhh0[r * HID + slot - 8];
    } else if (sec == 1) {
        if (slot == 6) w = ebih1[r] + ebhh1[r];
        else if (slot >= 8 && slot <= 71) w = eWih1[r * HID + slot - 8];
        else if (slot >= 72 && slot <= 135) w = eWhh1[r * HID + slot - 72];
    } else if (sec == 2) {
        if (slot < 2) w = dWih0[r * OUTD + slot];
        else if (slot == 6) w = dbih0[r] + dbhh0[r];
        else if (slot >= 8 && slot <= 71) w = dWhh0[r * HID + slot - 8];
    } else {
        if (slot == 6) w = dbih1[r] + dbhh1[r];
        else if (slot >= 8 && slot <= 71) w = dWih1[r * HID + slot - 8];
        else if (slot >= 72 && slot <= 135) w = dWhh1[r * HID + slot - 72];
    }
    __nv_bfloat16 h = __float2bfloat16(w);
    if (s) h = __float2bfloat16(w - __bfloat162float(h));
    int kx = (kk * 2) ^ ((n & 4) << 2);          // bank swizzle
    *(unsigned short*)(g_Wb + (size_t)g * GB + s * 8192 + n * 32 + kx) =
        __bfloat16_as_ushort(h);
}

// ---------------------------------------------------------------------------
__device__ __forceinline__ float sigmf(float x) {
    return __fdividef(1.f, 1.f + __expf(-x));
}
__device__ __forceinline__ float tanhf_(float x) {
    float e = __expf(2.f * x);
    return 1.f - __fdividef(2.f, e + 1.f);
}
__device__ __forceinline__ uint32_t smem_u32(const void* p) {
    uint32_t a;
    asm("{ .reg .u64 t; cvta.to.shared.u64 t, %1; cvt.u32.u64 %0, t; }" : "=r"(a) : "l"(p));
    return a;
}
__device__ __forceinline__ void cpa16(uint32_t s, const void* g) {
    asm volatile("cp.async.cg.shared.global [%0], [%1], 16;" :: "r"(s), "l"(g));
}
#define CPA_COMMIT() asm volatile("cp.async.commit_group;" ::: "memory")
#define CPA_WAIT0()  asm volatile("cp.async.wait_group 0;" ::: "memory")

__device__ __forceinline__ void mma_bf16(float* d, const uint32_t* a, const uint32_t* b) {
    asm volatile("mma.sync.aligned.m16n8k16.row.col.f32.bf16.bf16.f32 "
        "{%0,%1,%2,%3},{%4,%5,%6,%7},{%8,%9},{%0,%1,%2,%3};"
        : "+f"(d[0]), "+f"(d[1]), "+f"(d[2]), "+f"(d[3])
        : "r"(a[0]), "r"(a[1]), "r"(a[2]), "r"(a[3]), "r"(b[0]), "r"(b[1]));
}

__device__ __forceinline__ void split_st(__nv_bfloat16* H, __nv_bfloat16* L,
                                         int off, float v) {
    __nv_bfloat16 h = __float2bfloat16(v);
    H[off] = h;
    L[off] = __float2bfloat16(v - __bfloat162float(h));
}

// GEMM: acc[2][8][4] = A[64 x 16*ng] * B^T, warp tile m32 x n64, bf16 3-pass.
// B streamed via cp.async through a 2-slot 16KB ring.
__device__ __forceinline__ void do_gemm(const unsigned char* gW, int ng,
        const __nv_bfloat16* stgH, const __nv_bfloat16* stgL,
        const unsigned char* smb, uint32_t ringu,
        float (&acc)[2][8][4], int tid, int lane, int m0, int n0)
{
    #pragma unroll
    for (int a = 0; a < 2; a++)
        #pragma unroll
        for (int b = 0; b < 8; b++)
            #pragma unroll
            for (int c = 0; c < 4; c++) acc[a][b][c] = 0.f;
    const int r = lane >> 2, c2 = (lane & 3) * 2;

    #pragma unroll
    for (int e = 0; e < 4; e++)
        cpa16(ringu + (e * THREADS + tid) * 16, gW + (e * THREADS + tid) * 16);
    CPA_COMMIT();

    for (int g = 0; g < ng; g++) {
        CPA_WAIT0();
        __syncthreads();
        if (g + 1 < ng) {
            const unsigned char* src = gW + (size_t)(g + 1) * GB;
            uint32_t d = ringu + ((g + 1) & 1) * GB;
            #pragma unroll
            for (int e = 0; e < 4; e++)
                cpa16(d + (e * THREADS + tid) * 16, src + (e * THREADS + tid) * 16);
            CPA_COMMIT();
        }
        const int kb = g * 16;
        uint32_t ah[2][4], al[2][4];
        #pragma unroll
        for (int mt = 0; mt < 2; mt++) {
            int mb = m0 + mt * 16 + r;
            ah[mt][0] = *(const uint32_t*)(stgH + mb * KPAD + kb + c2);
            ah[mt][1] = *(const uint32_t*)(stgH + (mb + 8) * KPAD + kb + c2);
            ah[mt][2] = *(const uint32_t*)(stgH + mb * KPAD + kb + c2 + 8);
            ah[mt][3] = *(const uint32_t*)(stgH + (mb + 8) * KPAD + kb + c2 + 8);
            al[mt][0] = *(const uint32_t*)(stgL + mb * KPAD + kb + c2);
            al[mt][1] = *(const uint32_t*)(stgL + (mb + 8) * KPAD + kb + c2);
            al[mt][2] = *(const uint32_t*)(stgL + mb * KPAD + kb + c2 + 8);
            al[mt][3] = *(const uint32_t*)(stgL + (mb + 8) * KPAD + kb + c2 + 8);
        }
        const unsigned char* bs = smb + (g & 1) * GB;
        #pragma unroll
        for (int nt = 0; nt < 8; nt++) {
            int n = n0 + nt * 8 + r;
            int xr = (n & 4) << 2;
            const unsigned char* bp = bs + n * 32;
            uint32_t bh[2], bl[2];
            bh[0] = *(const uint32_t*)(bp + ((c2 * 2) ^ xr));
            bh[1] = *(const uint32_t*)(bp + ((c2 * 2 + 16) ^ xr));
            bl[0] = *(const uint32_t*)(bp + 8192 + ((c2 * 2) ^ xr));
            bl[1] = *(const uint32_t*)(bp + 8192 + ((c2 * 2 + 16) ^ xr));
            #pragma unroll
            for (int mt = 0; mt < 2; mt++) {
                mma_bf16(acc[mt][nt], ah[mt], bh);
                mma_bf16(acc[mt][nt], al[mt], bh);
                mma_bf16(acc[mt][nt], ah[mt], bl);
            }
        }
    }
    __syncthreads();
}

// Epilogue: thread owns 16 (m,j) cells with full i,f,g,o quads.
__device__ __forceinline__ void epi(float (&acc)[2][8][4], float* cst,
        __nv_bfloat16* stgH, __nv_bfloat16* stgL, int kh, int lane, int m0, int wn)
{
    const int r = lane >> 2, jl = lane & 3;
    #pragma unroll
    for (int mt = 0; mt < 2; mt++)
        #pragma unroll
        for (int rr = 0; rr < 2; rr++) {
            int m = m0 + mt * 16 + rr * 8 + r;
            #pragma unroll
            for (int u = 0; u < 4; u++) {
                float gi = acc[mt][2 * u][rr * 2 + 0];
                float gf = acc[mt][2 * u][rr * 2 + 1];
                float gg = acc[mt][2 * u + 1][rr * 2 + 0];
                float go = acc[mt][2 * u + 1][rr * 2 + 1];
                int ci = (mt * 2 + rr) * 4 + u;
                float cc = sigmf(gf) * cst[ci] + sigmf(gi) * tanhf_(gg);
                cst[ci] = cc;
                float h = sigmf(go) * tanhf_(cc);
                int j = wn * 16 + u * 4 + jl;
                split_st(stgH, stgL, m * KPAD + kh + j, h);
            }
        }
}

// ---------------------------------------------------------------------------
__global__ void __launch_bounds__(THREADS, 2)
lstm_mma(const float* __restrict__ hist, const float* __restrict__ linW,
         const float* __restrict__ linb, const float* __restrict__ start,
         float* __restrict__ out)
{
    extern __shared__ __align__(16) unsigned char sm[];
    __nv_bfloat16* stgH = (__nv_bfloat16*)(sm + STGH_OFF);
    __nv_bfloat16* stgL = (__nv_bfloat16*)(sm + STGL_OFF);
    float* lw = (float*)(sm + LW_OFF);
    float* lb = (float*)(sm + LB_OFF);
    uint32_t ringu = smem_u32(sm);

    const int tid = threadIdx.x, lane = tid & 31, wid = tid >> 5;
    const int m0 = (wid & 1) * 32, wn = wid >> 1, n0 = wn * 64;
    const int b0 = blockIdx.x * MT;

    for (int i = tid; i < MT * KPAD; i += THREADS) {
        stgH[i] = __float2bfloat16(0.f);
        stgL[i] = __float2bfloat16(0.f);
    }
    if (tid < 128) lw[tid] = linW[tid];
    if (tid < 2)   lb[tid] = linb[tid];
    __syncthreads();
    if (tid < MT) stgH[tid * KPAD + 6] = __float2bfloat16(1.f);   // bias feed

    float c0[16], c1[16];
    #pragma unroll
    for (int i = 0; i < 16; i++) { c0[i] = 0.f; c1[i] = 0.f; }
    float acc[2][8][4];

    // ---- anti-phase stagger: odd CTAs burn ~half a step on a dummy GEMM ----
    // With 2 co-resident CTAs this offsets their phases so one CTA's
    // tensor-pipe GEMM overlaps the other's MUFU-pipe epilogue.
    if (blockIdx.x & 1) {
        do_gemm(g_Wb + 5 * GB, 9, stgH, stgL, sm, ringu, acc, tid, lane, m0, n0);
        float s = 0.f;
        #pragma unroll
        for (int a = 0; a < 2; a++)
            #pragma unroll
            for (int b = 0; b < 8; b++)
                #pragma unroll
                for (int c = 0; c < 4; c++) s += acc[a][b][c];
        if (__float_as_uint(s) == 0xdeadbeefu)      // never true; keeps GEMM
            lb[0] = s;
        __syncthreads();
    }

    // ---------------- encoder ----------------
    for (int t = 0; t < SEQ; t++) {
        if (tid < MT) {
            const float* xp = hist + (size_t)(b0 + tid) * (AG * SEQ * IND) + t * IND;
            #pragma unroll
            for (int i = 0; i < IND; i++)
                split_st(stgH, stgL, tid * KPAD + i, xp[i]);
        }
        do_gemm(g_Wb,          5, stgH, stgL, sm, ringu, acc, tid, lane, m0, n0);
        epi(acc, c0, stgH, stgL, 8,  lane, m0, wn);
        do_gemm(g_Wb + 5 * GB, 9, stgH, stgL, sm, ringu, acc, tid, lane, m0, n0);
        epi(acc, c1, stgH, stgL, 72, lane, m0, wn);
    }

    // ---------------- start token ----------------
    __syncthreads();
    if (tid < MT) {
        split_st(stgH, stgL, tid * KPAD + 0, start[0]);
        split_st(stgH, stgL, tid * KPAD + 1, start[1]);
    }

    // ---------------- decoder ----------------
    for (int t = 0; t < TDEC; t++) {
        do_gemm(g_Wb + 14 * GB, 5, stgH, stgL, sm, ringu, acc, tid, lane, m0, n0);
        epi(acc, c0, stgH, stgL, 8,  lane, m0, wn);
        do_gemm(g_Wb + 19 * GB, 9, stgH, stgL, sm, ringu, acc, tid, lane, m0, n0);
        epi(acc, c1, stgH, stgL, 72, lane, m0, wn);
        __syncthreads();
        if (tid < 128) {
            int o = tid >> 6, m = tid & 63;
            float s = lb[o];
            const float* lwo = lw + o * 64;
            #pragma unroll 8
            for (int k = 0; k < HID; k++)
                s = fmaf(lwo[k], __bfloat162float(stgH[m * KPAD + 72 + k])
                               + __bfloat162float(stgL[m * KPAD + 72 + k]), s);
            out[(size_t)(b0 + m) * (TDEC * OUTD) + t * OUTD + o] = s;
            split_st(stgH, stgL, m * KPAD + o, s);
        }
        // next gemm's first barrier orders the feedback writes
    }
}

// ---------------------------------------------------------------------------
extern "C" void kernel_launch(void* const* d_in, const int* in_sizes, int n_in,
                              void* d_out, int out_size)
{
    (void)in_sizes; (void)n_in; (void)out_size;
    prep<<<(28 * 2 * 4096 + 255) / 256, 256>>>(
        (const float*)d_in[1],  (const float*)d_in[2],
        (const float*)d_in[3],  (const float*)d_in[4],
        (const float*)d_in[5],  (const float*)d_in[6],
        (const float*)d_in[7],  (const float*)d_in[8],
        (const float*)d_in[9],  (const float*)d_in[10],
        (const float*)d_in[11], (const float*)d_in[12],
        (const float*)d_in[13], (const float*)d_in[14],
        (const float*)d_in[15], (const float*)d_in[16]);

    cudaFuncSetAttribute(lstm_mma, cudaFuncAttributeMaxDynamicSharedMemorySize,
                         SM_TOT);
    lstm_mma<<<BATCH / MT, THREADS, SM_TOT>>>(
        (const float*)d_in[0], (const float*)d_in[17], (const float*)d_in[18],
        (const float*)d_in[19], (float*)d_out);
}